// round 8
// baseline (speedup 1.0000x reference)
#include <cuda_runtime.h>
#include <cuda_fp16.h>
#include <cstdint>
#include <cstddef>

// ---------------------------------------------------------------------------
#define BB 8
#define CC 256
#define SS 1024
#define NH 8
#define DK 256
#define HD 2048
#define QKVN 6144

#define BM 128
#define BN 128
#define BKF 32                     // K elements per block
#define PAD 40                     // fp16 per smem row (80B; ldsm conflict-free)
#define TILEB (128 * PAD * 2)      // 10240 B per tile
#define STAGEB (2 * TILEB)         // A, B
#define NSTAGE 4
#define SMEM_DYN (NSTAGE * STAGEB) // 81920 B (2 CTAs/SM)

typedef __half fp16;

// ---------------------------------------------------------------------------
// Device scratch (allocation-free)
// ---------------------------------------------------------------------------
__device__ __align__(128) fp16 g_xt[BB * SS * CC];        // [b*S+s][c]
__device__ __align__(128) fp16 g_WpT[QKVN * CC];          // [n][k]
__device__ __align__(128) fp16 g_WoT[CC * HD];            // [n][k]
__device__ __align__(128) fp16 g_q[BB * NH * SS * DK];    // [bh][s][d]
__device__ __align__(128) fp16 g_k[BB * NH * SS * DK];
__device__ __align__(128) fp16 g_v[BB * NH * SS * DK];
__device__ __align__(128) fp16 g_vt[BB * NH * DK * SS];   // [bh][d][s]
__device__ __align__(128) float g_scores[(size_t)BB * NH * SS * SS];
__device__ __align__(128) fp16 g_p[(size_t)BB * NH * SS * SS];
__device__ __align__(128) fp16 g_ao[BB * SS * HD];        // [b*S+s][h*DK+d]

// ---------------------------------------------------------------------------
// PTX helpers
// ---------------------------------------------------------------------------
__device__ __forceinline__ uint32_t smem_u32(const void* p) {
    uint32_t a;
    asm("{ .reg .u64 t; cvta.to.shared.u64 t, %1; cvt.u32.u64 %0, t; }"
        : "=r"(a) : "l"(p));
    return a;
}
__device__ __forceinline__ void cpa16(uint32_t dst, const void* src) {
    asm volatile("cp.async.cg.shared.global [%0], [%1], 16;"
                 :: "r"(dst), "l"(src) : "memory");
}
__device__ __forceinline__ void cpa_commit() {
    asm volatile("cp.async.commit_group;" ::: "memory");
}
template <int N> __device__ __forceinline__ void cpa_wait() {
    asm volatile("cp.async.wait_group %0;" :: "n"(N) : "memory");
}
__device__ __forceinline__ void ldsm4(uint32_t* r, uint32_t addr) {
    asm volatile("ldmatrix.sync.aligned.m8n8.x4.shared.b16 {%0,%1,%2,%3}, [%4];"
                 : "=r"(r[0]), "=r"(r[1]), "=r"(r[2]), "=r"(r[3]) : "r"(addr));
}
__device__ __forceinline__ void mma16816(float* d, const uint32_t* a,
                                         uint32_t b0, uint32_t b1) {
    asm volatile(
        "mma.sync.aligned.m16n8k16.row.col.f32.f16.f16.f32 "
        "{%0,%1,%2,%3}, {%4,%5,%6,%7}, {%8,%9}, {%0,%1,%2,%3};"
        : "+f"(d[0]), "+f"(d[1]), "+f"(d[2]), "+f"(d[3])
        : "r"(a[0]), "r"(a[1]), "r"(a[2]), "r"(a[3]), "r"(b0), "r"(b1));
}

// ---------------------------------------------------------------------------
// fp32 [Z][R][C] -> transposed fp16 [Z][C][R]
// ---------------------------------------------------------------------------
__global__ __launch_bounds__(256) void convT(const float* __restrict__ in,
                                             fp16* __restrict__ o, int R, int C) {
    __shared__ float t[32][33];
    int z = blockIdx.z;
    const float* I = in + (size_t)z * R * C;
    size_t ob = (size_t)z * R * C;
    int c0 = blockIdx.x * 32, r0 = blockIdx.y * 32;
    int x = threadIdx.x, y = threadIdx.y;
#pragma unroll
    for (int i = 0; i < 32; i += 8)
        t[y + i][x] = I[(size_t)(r0 + y + i) * C + c0 + x];
    __syncthreads();
#pragma unroll
    for (int i = 0; i < 32; i += 8)
        o[ob + (size_t)(c0 + y + i) * R + r0 + x] = __float2half(t[x][y + i]);
}

// ---------------------------------------------------------------------------
// fp16 transpose: [Z][R][C] -> [Z][C][R]
// ---------------------------------------------------------------------------
__global__ __launch_bounds__(256) void txph(const fp16* __restrict__ in,
                                            fp16* __restrict__ o, int R, int C) {
    __shared__ fp16 t[32][33];
    int z = blockIdx.z;
    size_t zb = (size_t)z * R * C;
    int c0 = blockIdx.x * 32, r0 = blockIdx.y * 32;
    int x = threadIdx.x, y = threadIdx.y;
#pragma unroll
    for (int i = 0; i < 32; i += 8)
        t[y + i][x] = in[zb + (size_t)(r0 + y + i) * C + c0 + x];
    __syncthreads();
#pragma unroll
    for (int i = 0; i < 32; i += 8)
        o[zb + (size_t)(c0 + y + i) * R + r0 + x] = t[x][y + i];
}

// ---------------------------------------------------------------------------
// fp16 GEMM: 4 warps, 64x64 warp tile, 4-stage cp.async.
// C tile = A[128,K] * B[128,K]^T
// MODE 0: QKV -> bias, scatter fp16 q/k/v
// MODE 1: QK^T -> scale, fp32 scores
// MODE 2: PV -> fp16 attnout
// MODE 3: proj -> bias + residual + transposed fp32 store
// ---------------------------------------------------------------------------
template <int MODE>
__global__ __launch_bounds__(128, 2) void gemm_fp16(
    const fp16* __restrict__ A, const fp16* __restrict__ B,
    float* __restrict__ C, fp16* __restrict__ Cf,
    int K, int ldA, int ldB, int ldC, size_t Az, size_t Bz, size_t Cz,
    const float* __restrict__ bias, const float* __restrict__ resid, float scale) {
    extern __shared__ __align__(16) char dynsm[];
    const uint32_t sbase = smem_u32(dynsm);

    const int tid = threadIdx.x;
    const int wid = tid >> 5;
    const int lane = tid & 31;
    const int wr = wid >> 1;   // warp row 0..1 (64 rows)
    const int wc = wid & 1;    // warp col 0..1 (64 cols)

    const int z = blockIdx.z;
    const int m0 = blockIdx.y * BM;
    const int n0 = blockIdx.x * BN;
    const fp16* tA = A + Az * z + (size_t)m0 * ldA;
    const fp16* tB = B + Bz * z + (size_t)n0 * ldB;
    const int NKB = K / BKF;

    // loader: thread t loads full row t of A and of B (4 x 16B each)
    auto issue = [&](int kb, int stg) {
        uint32_t sb = sbase + stg * STAGEB + tid * (PAD * 2);
        const fp16* ga = tA + (size_t)tid * ldA + kb * BKF;
        cpa16(sb, ga);
        cpa16(sb + 16, ga + 8);
        cpa16(sb + 32, ga + 16);
        cpa16(sb + 48, ga + 24);
        const fp16* gb = tB + (size_t)tid * ldB + kb * BKF;
        uint32_t sbb = sb + TILEB;
        cpa16(sbb, gb);
        cpa16(sbb + 16, gb + 8);
        cpa16(sbb + 32, gb + 16);
        cpa16(sbb + 48, gb + 24);
    };

    // ldmatrix per-lane offsets: 4 A frags (16 rows each), 4 B frags (16 cols each)
    const int lr = lane & 15, lhf = lane >> 4;
    uint32_t aoff[4], boff[4];
#pragma unroll
    for (int im = 0; im < 4; ++im)
        aoff[im] = ((wr * 64 + im * 16 + lr) * PAD + lhf * 8) * 2;
#pragma unroll
    for (int j4 = 0; j4 < 4; ++j4)
        boff[j4] = ((wc * 64 + j4 * 16 + lr) * PAD + lhf * 8) * 2;

    float acc[4][8][4] = {};

    issue(0, 0); cpa_commit();
    if (NKB > 1) { issue(1, 1); cpa_commit(); }
    if (NKB > 2) { issue(2, 2); cpa_commit(); }

    for (int kb = 0; kb < NKB; ++kb) {
        if (kb + 3 <= NKB) cpa_wait<2>();
        else if (kb + 2 == NKB) cpa_wait<1>();
        else cpa_wait<0>();
        __syncthreads();
        if (kb + 3 < NKB) { issue(kb + 3, (kb + 3) % NSTAGE); cpa_commit(); }

        const int stg = kb % NSTAGE;
        const uint32_t sA = sbase + stg * STAGEB;
        const uint32_t sB = sA + TILEB;

#pragma unroll
        for (int ks = 0; ks < 2; ++ks) {
            const uint32_t kso = ks * 32;
            uint32_t af[4][4], bf[4][4];
#pragma unroll
            for (int im = 0; im < 4; ++im) ldsm4(af[im], sA + aoff[im] + kso);
#pragma unroll
            for (int j4 = 0; j4 < 4; ++j4) ldsm4(bf[j4], sB + boff[j4] + kso);
#pragma unroll
            for (int im = 0; im < 4; ++im)
#pragma unroll
                for (int j4 = 0; j4 < 4; ++j4) {
                    mma16816(acc[im][j4 * 2], af[im], bf[j4][0], bf[j4][2]);
                    mma16816(acc[im][j4 * 2 + 1], af[im], bf[j4][1], bf[j4][3]);
                }
        }
    }
    __syncthreads();

    // ---- epilogue: warp covers rows wr*64 + im*16 + r0l(+8), cols wc*64 + jn*8 + c0l
    const int r0l = lane >> 2;
    const int c0l = (lane & 3) * 2;

    if (MODE == 0) {
        const int hB = n0 / 768;
        const int loc0 = n0 % 768;
        const int seg = loc0 >> 8;
        const int d0 = loc0 & 255;
        fp16* dst = (seg == 0) ? g_q : (seg == 1) ? g_k : g_v;
#pragma unroll
        for (int im = 0; im < 4; ++im)
#pragma unroll
            for (int jn = 0; jn < 8; ++jn)
#pragma unroll
                for (int p = 0; p < 2; ++p) {
                    int m = m0 + wr * 64 + im * 16 + r0l + p * 8;
                    int nb = wc * 64 + jn * 8 + c0l;
                    int b = m >> 10, s2 = m & 1023;
                    size_t row = ((size_t)(b * NH + hB) * SS + s2) * DK + d0 + nb;
                    __half2 h;
                    h.x = __float2half(acc[im][jn][p * 2] + bias[n0 + nb]);
                    h.y = __float2half(acc[im][jn][p * 2 + 1] + bias[n0 + nb + 1]);
                    *(__half2*)(dst + row) = h;
                }
    } else if (MODE == 1) {
        float* Cb = C + Cz * z;
#pragma unroll
        for (int im = 0; im < 4; ++im)
#pragma unroll
            for (int jn = 0; jn < 8; ++jn)
#pragma unroll
                for (int p = 0; p < 2; ++p) {
                    int m = m0 + wr * 64 + im * 16 + r0l + p * 8;
                    int nb = wc * 64 + jn * 8 + c0l;
                    float2 o;
                    o.x = acc[im][jn][p * 2] * scale;
                    o.y = acc[im][jn][p * 2 + 1] * scale;
                    *(float2*)(Cb + (size_t)m * ldC + n0 + nb) = o;
                }
    } else if (MODE == 2) {
        int b = z >> 3, h2 = z & 7;
        size_t base = (size_t)b * SS * HD + h2 * DK;
#pragma unroll
        for (int im = 0; im < 4; ++im)
#pragma unroll
            for (int jn = 0; jn < 8; ++jn)
#pragma unroll
                for (int p = 0; p < 2; ++p) {
                    int m = m0 + wr * 64 + im * 16 + r0l + p * 8;
                    int nb = wc * 64 + jn * 8 + c0l;
                    size_t idx = base + (size_t)m * HD + n0 + nb;
                    __half2 h;
                    h.x = __float2half(acc[im][jn][p * 2]);
                    h.y = __float2half(acc[im][jn][p * 2 + 1]);
                    *(__half2*)(g_ao + idx) = h;
                }
    } else {  // MODE 3: smem transpose -> coalesced [B,C,S] store + bias + resid
        float* sc = (float*)dynsm;  // 128 x 65 fp32 = 33.3 KB (fits 80 KB)
        const int bB = m0 >> 10;
        const int s0 = m0 & 1023;
#pragma unroll
        for (int pass = 0; pass < 2; ++pass) {
            __syncthreads();
            if (wc == pass) {
#pragma unroll
                for (int im = 0; im < 4; ++im)
#pragma unroll
                    for (int jn = 0; jn < 8; ++jn)
#pragma unroll
                        for (int p = 0; p < 2; ++p) {
                            int rloc = wr * 64 + im * 16 + r0l + p * 8;
                            int cloc = jn * 8 + c0l;
                            sc[rloc * 65 + cloc] = acc[im][jn][p * 2];
                            sc[rloc * 65 + cloc + 1] = acc[im][jn][p * 2 + 1];
                        }
            }
            __syncthreads();
            // 128 threads: thread -> n col (64 of them) x s-half (2)
            int nl = tid & 63;
            int sblk = (tid >> 6) * 64;   // 0 or 64
            int n = n0 + pass * 64 + nl;
            size_t obase = (((size_t)(bB * CC + n)) << 10) + s0 + sblk;
            float bn = bias[n];
#pragma unroll
            for (int j = 0; j < 64; j += 4) {
                float4 xr = *(const float4*)(resid + obase + j);
                float4 o;
                o.x = sc[(sblk + j + 0) * 65 + nl] + bn + xr.x;
                o.y = sc[(sblk + j + 1) * 65 + nl] + bn + xr.y;
                o.z = sc[(sblk + j + 2) * 65 + nl] + bn + xr.z;
                o.w = sc[(sblk + j + 3) * 65 + nl] + bn + xr.w;
                *(float4*)(C + obase + j) = o;
            }
        }
    }
}

// ---------------------------------------------------------------------------
// Row softmax over 1024 cols: fp32 scores -> fp16 P
// ---------------------------------------------------------------------------
__global__ __launch_bounds__(256) void softmax_kernel() {
    size_t row = blockIdx.x;
    const float* p = g_scores + (row << 10);
    int tid = threadIdx.x;
    float4 v = reinterpret_cast<const float4*>(p)[tid];

    float m = fmaxf(fmaxf(v.x, v.y), fmaxf(v.z, v.w));
#pragma unroll
    for (int o = 16; o; o >>= 1) m = fmaxf(m, __shfl_xor_sync(0xffffffffu, m, o));
    __shared__ float redm[8], reds[8];
    if ((tid & 31) == 0) redm[tid >> 5] = m;
    __syncthreads();
    m = redm[0];
#pragma unroll
    for (int w = 1; w < 8; ++w) m = fmaxf(m, redm[w]);

    v.x = __expf(v.x - m); v.y = __expf(v.y - m);
    v.z = __expf(v.z - m); v.w = __expf(v.w - m);
    float s = v.x + v.y + v.z + v.w;
#pragma unroll
    for (int o = 16; o; o >>= 1) s += __shfl_xor_sync(0xffffffffu, s, o);
    if ((tid & 31) == 0) reds[tid >> 5] = s;
    __syncthreads();
    s = reds[0];
#pragma unroll
    for (int w = 1; w < 8; ++w) s += reds[w];

    float inv = 1.0f / s;
    __half2 h0, h1;
    h0.x = __float2half(v.x * inv); h0.y = __float2half(v.y * inv);
    h1.x = __float2half(v.z * inv); h1.y = __float2half(v.w * inv);
    size_t ob = (row << 10) + tid * 4;
    *(__half2*)(g_p + ob) = h0;
    *(__half2*)(g_p + ob + 2) = h1;
}

// ---------------------------------------------------------------------------
extern "C" void kernel_launch(void* const* d_in, const int* in_sizes, int n_in,
                              void* d_out, int out_size) {
    const float* x  = (const float*)d_in[0];
    const float* Wp = (const float*)d_in[1];
    const float* bp = (const float*)d_in[2];
    const float* Wo = (const float*)d_in[3];
    const float* bo = (const float*)d_in[4];
    float* out = (float*)d_out;

    fp16 *xt, *WpT, *WoT, *q, *k, *v, *vt, *pp, *ao;
    float* sc;
    cudaGetSymbolAddress((void**)&xt, g_xt);
    cudaGetSymbolAddress((void**)&WpT, g_WpT);
    cudaGetSymbolAddress((void**)&WoT, g_WoT);
    cudaGetSymbolAddress((void**)&q, g_q);
    cudaGetSymbolAddress((void**)&k, g_k);
    cudaGetSymbolAddress((void**)&v, g_v);
    cudaGetSymbolAddress((void**)&vt, g_vt);
    cudaGetSymbolAddress((void**)&pp, g_p);
    cudaGetSymbolAddress((void**)&ao, g_ao);
    cudaGetSymbolAddress((void**)&sc, g_scores);

    cudaFuncSetAttribute(gemm_fp16<0>, cudaFuncAttributeMaxDynamicSharedMemorySize, SMEM_DYN);
    cudaFuncSetAttribute(gemm_fp16<1>, cudaFuncAttributeMaxDynamicSharedMemorySize, SMEM_DYN);
    cudaFuncSetAttribute(gemm_fp16<2>, cudaFuncAttributeMaxDynamicSharedMemorySize, SMEM_DYN);
    cudaFuncSetAttribute(gemm_fp16<3>, cudaFuncAttributeMaxDynamicSharedMemorySize, SMEM_DYN);

    dim3 tb(32, 8);
    convT<<<dim3(SS / 32, CC / 32, BB), tb>>>(x, xt, CC, SS);
    convT<<<dim3(QKVN / 32, CC / 32, 1), tb>>>(Wp, WpT, CC, QKVN);
    convT<<<dim3(CC / 32, HD / 32, 1), tb>>>(Wo, WoT, HD, CC);

    // QKV projection: [8192,256] @ [6144,256]^T
    gemm_fp16<0><<<dim3(QKVN / BN, (BB * SS) / BM, 1), 128, SMEM_DYN>>>(
        xt, WpT, nullptr, nullptr, CC, CC, CC, 0, 0, 0, 0, bp, nullptr, 1.0f);

    // V -> V^T per head
    txph<<<dim3(DK / 32, SS / 32, BB * NH), tb>>>(v, vt, SS, DK);

    // Q K^T (scaled)
    gemm_fp16<1><<<dim3(SS / BN, SS / BM, BB * NH), 128, SMEM_DYN>>>(
        q, k, sc, nullptr, DK, DK, DK, SS,
        (size_t)SS * DK, (size_t)SS * DK, (size_t)SS * SS, nullptr, nullptr, 0.0625f);

    softmax_kernel<<<BB * NH * SS, 256>>>();

    // P V
    gemm_fp16<2><<<dim3(DK / BN, SS / BM, BB * NH), 128, SMEM_DYN>>>(
        pp, vt, nullptr, nullptr, SS, SS, SS, 0,
        (size_t)SS * SS, (size_t)DK * SS, 0, nullptr, nullptr, 1.0f);

    // Out projection + bias + residual
    gemm_fp16<3><<<dim3(CC / BN, (BB * SS) / BM, 1), 128, SMEM_DYN>>>(
        ao, WoT, out, nullptr, HD, HD, HD, 0, 0, 0, 0, bo, x, 1.0f);
}

// round 9
// speedup vs baseline: 1.8117x; 1.8117x over previous
#include <cuda_runtime.h>
#include <cuda_fp16.h>
#include <cstdint>
#include <cstddef>

// ---------------------------------------------------------------------------
#define BB 8
#define CC 256
#define SS 1024
#define NH 8
#define DK 256
#define HD 2048
#define QKVN 6144

#define BM 128
#define BN 128
#define BKF 32            // K elements per block
#define PAD 40            // fp16 per smem row (80B; ldsm conflict-free)
#define TILEE (128 * PAD) // fp16 elements per tile

typedef __half fp16;

// ---------------------------------------------------------------------------
// Device scratch (allocation-free)
// ---------------------------------------------------------------------------
__device__ __align__(128) fp16 g_xt[BB * SS * CC];        // [b*S+s][c]
__device__ __align__(128) fp16 g_WpT[QKVN * CC];          // [n][k]
__device__ __align__(128) fp16 g_WoT[CC * HD];            // [n][k]
__device__ __align__(128) fp16 g_q[BB * NH * SS * DK];    // [bh][s][d]
__device__ __align__(128) fp16 g_k[BB * NH * SS * DK];
__device__ __align__(128) fp16 g_v[BB * NH * SS * DK];
__device__ __align__(128) fp16 g_vt[BB * NH * DK * SS];   // [bh][d][s]
__device__ __align__(128) float g_scores[(size_t)BB * NH * SS * SS];
__device__ __align__(128) fp16 g_p[(size_t)BB * NH * SS * SS];
__device__ __align__(128) fp16 g_ao[BB * SS * HD];        // [b*S+s][h*DK+d]

// ---------------------------------------------------------------------------
// PTX helpers
// ---------------------------------------------------------------------------
__device__ __forceinline__ uint32_t smem_u32(const void* p) {
    uint32_t a;
    asm("{ .reg .u64 t; cvta.to.shared.u64 t, %1; cvt.u32.u64 %0, t; }"
        : "=r"(a) : "l"(p));
    return a;
}
__device__ __forceinline__ void ldsm4(uint32_t* r, uint32_t addr) {
    asm volatile("ldmatrix.sync.aligned.m8n8.x4.shared.b16 {%0,%1,%2,%3}, [%4];"
                 : "=r"(r[0]), "=r"(r[1]), "=r"(r[2]), "=r"(r[3]) : "r"(addr));
}
__device__ __forceinline__ void mma16816(float* d, const uint32_t* a,
                                         uint32_t b0, uint32_t b1) {
    asm volatile(
        "mma.sync.aligned.m16n8k16.row.col.f32.f16.f16.f32 "
        "{%0,%1,%2,%3}, {%4,%5,%6,%7}, {%8,%9}, {%0,%1,%2,%3};"
        : "+f"(d[0]), "+f"(d[1]), "+f"(d[2]), "+f"(d[3])
        : "r"(a[0]), "r"(a[1]), "r"(a[2]), "r"(a[3]), "r"(b0), "r"(b1));
}

// ---------------------------------------------------------------------------
// fp32 [Z][R][C] -> transposed fp16 [Z][C][R]
// ---------------------------------------------------------------------------
__global__ __launch_bounds__(256) void convT(const float* __restrict__ in,
                                             fp16* __restrict__ o, int R, int C) {
    __shared__ float t[32][33];
    int z = blockIdx.z;
    const float* I = in + (size_t)z * R * C;
    size_t ob = (size_t)z * R * C;
    int c0 = blockIdx.x * 32, r0 = blockIdx.y * 32;
    int x = threadIdx.x, y = threadIdx.y;
#pragma unroll
    for (int i = 0; i < 32; i += 8)
        t[y + i][x] = I[(size_t)(r0 + y + i) * C + c0 + x];
    __syncthreads();
#pragma unroll
    for (int i = 0; i < 32; i += 8)
        o[ob + (size_t)(c0 + y + i) * R + r0 + x] = __float2half(t[x][y + i]);
}

// ---------------------------------------------------------------------------
// fp16 transpose: [Z][R][C] -> [Z][C][R]
// ---------------------------------------------------------------------------
__global__ __launch_bounds__(256) void txph(const fp16* __restrict__ in,
                                            fp16* __restrict__ o, int R, int C) {
    __shared__ fp16 t[32][33];
    int z = blockIdx.z;
    size_t zb = (size_t)z * R * C;
    int c0 = blockIdx.x * 32, r0 = blockIdx.y * 32;
    int x = threadIdx.x, y = threadIdx.y;
#pragma unroll
    for (int i = 0; i < 32; i += 8)
        t[y + i][x] = in[zb + (size_t)(r0 + y + i) * C + c0 + x];
    __syncthreads();
#pragma unroll
    for (int i = 0; i < 32; i += 8)
        o[zb + (size_t)(c0 + y + i) * R + r0 + x] = t[x][y + i];
}

// ---------------------------------------------------------------------------
// fp16 GEMM: LDG->reg->STS double buffer, ONE sync per K-block.
// C tile = A[128,K] * B[128,K]^T, 8 warps (4x2), 32x64 warp tile.
// MODE 0: QKV -> bias, scatter fp16 q/k/v
// MODE 1: QK^T -> scale, fp32 scores
// MODE 2: PV -> fp16 attnout
// MODE 3: proj -> bias + residual + transposed fp32 store
// ---------------------------------------------------------------------------
template <int MODE>
__global__ __launch_bounds__(256) void gemm_fp16(
    const fp16* __restrict__ A, const fp16* __restrict__ B,
    float* __restrict__ C, fp16* __restrict__ Cf,
    int K, int ldA, int ldB, int ldC, size_t Az, size_t Bz, size_t Cz,
    const float* __restrict__ bias, const float* __restrict__ resid, float scale) {
    // [stage][A=0/B=1][128*PAD] : 2*2*5120*2B = 40 KB static
    __shared__ __align__(16) fp16 smt[2][2][TILEE];

    const int tid = threadIdx.x;
    const int wid = tid >> 5;
    const int lane = tid & 31;
    const int wr = wid >> 1;   // warp row 0..3 (32 rows)
    const int wc = wid & 1;    // warp col 0..1 (64 cols)

    const int z = blockIdx.z;
    const int m0 = blockIdx.y * BM;
    const int n0 = blockIdx.x * BN;
    const fp16* tA = A + Az * z + (size_t)m0 * ldA;
    const fp16* tB = B + Bz * z + (size_t)n0 * ldB;
    const int NKB = K / BKF;

    // loader: row = tid>>1 (0..127), 16-elem half = (tid&1)*16
    const int crow = tid >> 1;
    const int ccol = (tid & 1) * 16;

    uint4 ra0, ra1, rb0, rb1;
    auto ldg = [&](int kb) {
        const fp16* ga = tA + (size_t)crow * ldA + kb * BKF + ccol;
        ra0 = *(const uint4*)ga;
        ra1 = *(const uint4*)(ga + 8);
        const fp16* gb = tB + (size_t)crow * ldB + kb * BKF + ccol;
        rb0 = *(const uint4*)gb;
        rb1 = *(const uint4*)(gb + 8);
    };
    auto sts = [&](int st) {
        fp16* da = &smt[st][0][crow * PAD + ccol];
        *(uint4*)da = ra0;
        *(uint4*)(da + 8) = ra1;
        fp16* db = &smt[st][1][crow * PAD + ccol];
        *(uint4*)db = rb0;
        *(uint4*)(db + 8) = rb1;
    };

    // ldmatrix per-lane offsets
    const int lr = lane & 15, lhf = lane >> 4;
    uint32_t aoff[2], boff[4];
#pragma unroll
    for (int im = 0; im < 2; ++im)
        aoff[im] = ((wr * 32 + im * 16 + lr) * PAD + lhf * 8) * 2;
#pragma unroll
    for (int jn = 0; jn < 4; ++jn)
        boff[jn] = ((wc * 64 + jn * 16 + lr) * PAD + lhf * 8) * 2;

    float acc[2][8][4] = {};

    ldg(0);
    for (int kb = 0; kb < NKB; ++kb) {
        const int st = kb & 1;
        sts(st);                      // buf[st] last read by compute(kb-2): safe
        __syncthreads();
        if (kb + 1 < NKB) ldg(kb + 1);  // in flight during compute

        const uint32_t sA = smem_u32(&smt[st][0][0]);
        const uint32_t sB = smem_u32(&smt[st][1][0]);
#pragma unroll
        for (int ks = 0; ks < 2; ++ks) {
            const uint32_t kso = ks * 32;
            uint32_t af[2][4], bf[4][4];
            ldsm4(af[0], sA + aoff[0] + kso);
            ldsm4(af[1], sA + aoff[1] + kso);
#pragma unroll
            for (int jn = 0; jn < 4; ++jn) ldsm4(bf[jn], sB + boff[jn] + kso);
#pragma unroll
            for (int im = 0; im < 2; ++im)
#pragma unroll
                for (int jn = 0; jn < 4; ++jn) {
                    mma16816(acc[im][jn * 2], af[im], bf[jn][0], bf[jn][2]);
                    mma16816(acc[im][jn * 2 + 1], af[im], bf[jn][1], bf[jn][3]);
                }
        }
    }
    __syncthreads();

    // ---- epilogue ----
    const int r0l = lane >> 2;
    const int c0l = (lane & 3) * 2;

    if (MODE == 0) {
        const int hB = n0 / 768;
        const int loc0 = n0 % 768;
        const int seg = loc0 >> 8;
        const int d0 = loc0 & 255;
        fp16* dst = (seg == 0) ? g_q : (seg == 1) ? g_k : g_v;
#pragma unroll
        for (int im = 0; im < 2; ++im)
#pragma unroll
            for (int jn = 0; jn < 8; ++jn)
#pragma unroll
                for (int p = 0; p < 2; ++p) {
                    int m = m0 + wr * 32 + im * 16 + r0l + p * 8;
                    int nb = wc * 64 + jn * 8 + c0l;
                    int b = m >> 10, s2 = m & 1023;
                    size_t row = ((size_t)(b * NH + hB) * SS + s2) * DK + d0 + nb;
                    __half2 h;
                    h.x = __float2half(acc[im][jn][p * 2] + bias[n0 + nb]);
                    h.y = __float2half(acc[im][jn][p * 2 + 1] + bias[n0 + nb + 1]);
                    *(__half2*)(dst + row) = h;
                }
    } else if (MODE == 1) {
        float* Cb = C + Cz * z;
#pragma unroll
        for (int im = 0; im < 2; ++im)
#pragma unroll
            for (int jn = 0; jn < 8; ++jn)
#pragma unroll
                for (int p = 0; p < 2; ++p) {
                    int m = m0 + wr * 32 + im * 16 + r0l + p * 8;
                    int nb = wc * 64 + jn * 8 + c0l;
                    float2 o;
                    o.x = acc[im][jn][p * 2] * scale;
                    o.y = acc[im][jn][p * 2 + 1] * scale;
                    *(float2*)(Cb + (size_t)m * ldC + n0 + nb) = o;
                }
    } else if (MODE == 2) {
        int b = z >> 3, h2 = z & 7;
        size_t base = (size_t)b * SS * HD + h2 * DK;
#pragma unroll
        for (int im = 0; im < 2; ++im)
#pragma unroll
            for (int jn = 0; jn < 8; ++jn)
#pragma unroll
                for (int p = 0; p < 2; ++p) {
                    int m = m0 + wr * 32 + im * 16 + r0l + p * 8;
                    int nb = wc * 64 + jn * 8 + c0l;
                    size_t idx = base + (size_t)m * HD + n0 + nb;
                    __half2 h;
                    h.x = __float2half(acc[im][jn][p * 2]);
                    h.y = __float2half(acc[im][jn][p * 2 + 1]);
                    *(__half2*)(g_ao + idx) = h;
                }
    } else {  // MODE 3: smem transpose -> coalesced [B,C,S] store + bias + resid
        float* sc = (float*)&smt[0][0][0];  // 128 x 65 fp32 = 33.3 KB (fits 40 KB)
        const int bB = m0 >> 10;
        const int s0 = m0 & 1023;
#pragma unroll
        for (int pass = 0; pass < 2; ++pass) {
            __syncthreads();
            if (wc == pass) {
#pragma unroll
                for (int im = 0; im < 2; ++im)
#pragma unroll
                    for (int jn = 0; jn < 8; ++jn)
#pragma unroll
                        for (int p = 0; p < 2; ++p) {
                            int rloc = wr * 32 + im * 16 + r0l + p * 8;
                            int cloc = jn * 8 + c0l;
                            sc[rloc * 65 + cloc] = acc[im][jn][p * 2];
                            sc[rloc * 65 + cloc + 1] = acc[im][jn][p * 2 + 1];
                        }
            }
            __syncthreads();
            int nl = tid >> 2;
            int sblk = (tid & 3) * 32;
            int n = n0 + pass * 64 + nl;
            size_t obase = (((size_t)(bB * CC + n)) << 10) + s0 + sblk;
            float bn = bias[n];
#pragma unroll
            for (int j = 0; j < 32; j += 4) {
                float4 xr = *(const float4*)(resid + obase + j);
                float4 o;
                o.x = sc[(sblk + j + 0) * 65 + nl] + bn + xr.x;
                o.y = sc[(sblk + j + 1) * 65 + nl] + bn + xr.y;
                o.z = sc[(sblk + j + 2) * 65 + nl] + bn + xr.z;
                o.w = sc[(sblk + j + 3) * 65 + nl] + bn + xr.w;
                *(float4*)(C + obase + j) = o;
            }
        }
    }
}

// ---------------------------------------------------------------------------
// Row softmax over 1024 cols: fp32 scores -> fp16 P
// ---------------------------------------------------------------------------
__global__ __launch_bounds__(256) void softmax_kernel() {
    size_t row = blockIdx.x;
    const float* p = g_scores + (row << 10);
    int tid = threadIdx.x;
    float4 v = reinterpret_cast<const float4*>(p)[tid];

    float m = fmaxf(fmaxf(v.x, v.y), fmaxf(v.z, v.w));
#pragma unroll
    for (int o = 16; o; o >>= 1) m = fmaxf(m, __shfl_xor_sync(0xffffffffu, m, o));
    __shared__ float redm[8], reds[8];
    if ((tid & 31) == 0) redm[tid >> 5] = m;
    __syncthreads();
    m = redm[0];
#pragma unroll
    for (int w = 1; w < 8; ++w) m = fmaxf(m, redm[w]);

    v.x = __expf(v.x - m); v.y = __expf(v.y - m);
    v.z = __expf(v.z - m); v.w = __expf(v.w - m);
    float s = v.x + v.y + v.z + v.w;
#pragma unroll
    for (int o = 16; o; o >>= 1) s += __shfl_xor_sync(0xffffffffu, s, o);
    if ((tid & 31) == 0) reds[tid >> 5] = s;
    __syncthreads();
    s = reds[0];
#pragma unroll
    for (int w = 1; w < 8; ++w) s += reds[w];

    float inv = 1.0f / s;
    __half2 h0, h1;
    h0.x = __float2half(v.x * inv); h0.y = __float2half(v.y * inv);
    h1.x = __float2half(v.z * inv); h1.y = __float2half(v.w * inv);
    size_t ob = (row << 10) + tid * 4;
    *(__half2*)(g_p + ob) = h0;
    *(__half2*)(g_p + ob + 2) = h1;
}

// ---------------------------------------------------------------------------
extern "C" void kernel_launch(void* const* d_in, const int* in_sizes, int n_in,
                              void* d_out, int out_size) {
    const float* x  = (const float*)d_in[0];
    const float* Wp = (const float*)d_in[1];
    const float* bp = (const float*)d_in[2];
    const float* Wo = (const float*)d_in[3];
    const float* bo = (const float*)d_in[4];
    float* out = (float*)d_out;

    fp16 *xt, *WpT, *WoT, *q, *k, *v, *vt, *pp, *ao;
    float* sc;
    cudaGetSymbolAddress((void**)&xt, g_xt);
    cudaGetSymbolAddress((void**)&WpT, g_WpT);
    cudaGetSymbolAddress((void**)&WoT, g_WoT);
    cudaGetSymbolAddress((void**)&q, g_q);
    cudaGetSymbolAddress((void**)&k, g_k);
    cudaGetSymbolAddress((void**)&v, g_v);
    cudaGetSymbolAddress((void**)&vt, g_vt);
    cudaGetSymbolAddress((void**)&pp, g_p);
    cudaGetSymbolAddress((void**)&ao, g_ao);
    cudaGetSymbolAddress((void**)&sc, g_scores);

    dim3 tb(32, 8);
    convT<<<dim3(SS / 32, CC / 32, BB), tb>>>(x, xt, CC, SS);
    convT<<<dim3(QKVN / 32, CC / 32, 1), tb>>>(Wp, WpT, CC, QKVN);
    convT<<<dim3(CC / 32, HD / 32, 1), tb>>>(Wo, WoT, HD, CC);

    // QKV projection: [8192,256] @ [6144,256]^T
    gemm_fp16<0><<<dim3(QKVN / BN, (BB * SS) / BM, 1), 256>>>(
        xt, WpT, nullptr, nullptr, CC, CC, CC, 0, 0, 0, 0, bp, nullptr, 1.0f);

    // V -> V^T per head
    txph<<<dim3(DK / 32, SS / 32, BB * NH), tb>>>(v, vt, SS, DK);

    // Q K^T (scaled)
    gemm_fp16<1><<<dim3(SS / BN, SS / BM, BB * NH), 256>>>(
        q, k, sc, nullptr, DK, DK, DK, SS,
        (size_t)SS * DK, (size_t)SS * DK, (size_t)SS * SS, nullptr, nullptr, 0.0625f);

    softmax_kernel<<<BB * NH * SS, 256>>>();

    // P V
    gemm_fp16<2><<<dim3(DK / BN, SS / BM, BB * NH), 256>>>(
        pp, vt, nullptr, nullptr, SS, SS, SS, 0,
        (size_t)SS * SS, (size_t)DK * SS, 0, nullptr, nullptr, 1.0f);

    // Out projection + bias + residual
    gemm_fp16<3><<<dim3(CC / BN, (BB * SS) / BM, 1), 256>>>(
        ao, WoT, out, nullptr, HD, HD, HD, 0, 0, 0, 0, bo, x, 1.0f);
}

// round 10
// speedup vs baseline: 2.2240x; 1.2276x over previous
#include <cuda_runtime.h>
#include <cuda_fp16.h>
#include <cstdint>
#include <cstddef>

// ---------------------------------------------------------------------------
#define BB 8
#define CC 256
#define SS 1024
#define NH 8
#define DK 256
#define HD 2048
#define QKVN 6144

#define BM 128
#define BN 128
#define BKF 32                     // K elements per block
#define PAD 40                     // fp16 per smem row (80B; ldsm conflict-free)
#define TILEB (128 * PAD * 2)      // 10240 B per tile
#define STAGEB (2 * TILEB)         // A, B
#define NSTAGE 4
#define SMEM_DYN (NSTAGE * STAGEB) // 81920 B (2 CTAs/SM)

typedef __half fp16;

// ---------------------------------------------------------------------------
// Device scratch (allocation-free)
// ---------------------------------------------------------------------------
__device__ __align__(128) fp16 g_xt[BB * SS * CC];        // [b*S+s][c]
__device__ __align__(128) fp16 g_WpT[QKVN * CC];          // [n][k]
__device__ __align__(128) fp16 g_WoT[CC * HD];            // [n][k]
__device__ __align__(128) fp16 g_q[BB * NH * SS * DK];    // [bh][s][d]
__device__ __align__(128) fp16 g_k[BB * NH * SS * DK];
__device__ __align__(128) fp16 g_v[BB * NH * SS * DK];
__device__ __align__(128) fp16 g_vt[BB * NH * DK * SS];   // [bh][d][s]
__device__ __align__(128) fp16 g_p[(size_t)BB * NH * SS * SS]; // unnormalized exp
__device__ __align__(128) float g_l[BB * NH * SS];        // row sums of exp
__device__ __align__(128) fp16 g_ao[BB * SS * HD];        // [b*S+s][h*DK+d]

// ---------------------------------------------------------------------------
// PTX helpers
// ---------------------------------------------------------------------------
__device__ __forceinline__ uint32_t smem_u32(const void* p) {
    uint32_t a;
    asm("{ .reg .u64 t; cvta.to.shared.u64 t, %1; cvt.u32.u64 %0, t; }"
        : "=r"(a) : "l"(p));
    return a;
}
__device__ __forceinline__ void cpa16(uint32_t dst, const void* src) {
    asm volatile("cp.async.cg.shared.global [%0], [%1], 16;"
                 :: "r"(dst), "l"(src) : "memory");
}
__device__ __forceinline__ void cpa_commit() {
    asm volatile("cp.async.commit_group;" ::: "memory");
}
template <int N> __device__ __forceinline__ void cpa_wait() {
    asm volatile("cp.async.wait_group %0;" :: "n"(N) : "memory");
}
__device__ __forceinline__ void ldsm4(uint32_t* r, uint32_t addr) {
    asm volatile("ldmatrix.sync.aligned.m8n8.x4.shared.b16 {%0,%1,%2,%3}, [%4];"
                 : "=r"(r[0]), "=r"(r[1]), "=r"(r[2]), "=r"(r[3]) : "r"(addr));
}
__device__ __forceinline__ void mma16816(float* d, const uint32_t* a,
                                         uint32_t b0, uint32_t b1) {
    asm volatile(
        "mma.sync.aligned.m16n8k16.row.col.f32.f16.f16.f32 "
        "{%0,%1,%2,%3}, {%4,%5,%6,%7}, {%8,%9}, {%0,%1,%2,%3};"
        : "+f"(d[0]), "+f"(d[1]), "+f"(d[2]), "+f"(d[3])
        : "r"(a[0]), "r"(a[1]), "r"(a[2]), "r"(a[3]), "r"(b0), "r"(b1));
}

// ---------------------------------------------------------------------------
// fp32 [Z][R][C] -> transposed fp16 [Z][C][R]
// ---------------------------------------------------------------------------
__global__ __launch_bounds__(256) void convT(const float* __restrict__ in,
                                             fp16* __restrict__ o, int R, int C) {
    __shared__ float t[32][33];
    int z = blockIdx.z;
    const float* I = in + (size_t)z * R * C;
    size_t ob = (size_t)z * R * C;
    int c0 = blockIdx.x * 32, r0 = blockIdx.y * 32;
    int x = threadIdx.x, y = threadIdx.y;
#pragma unroll
    for (int i = 0; i < 32; i += 8)
        t[y + i][x] = I[(size_t)(r0 + y + i) * C + c0 + x];
    __syncthreads();
#pragma unroll
    for (int i = 0; i < 32; i += 8)
        o[ob + (size_t)(c0 + y + i) * R + r0 + x] = __float2half(t[x][y + i]);
}

// ---------------------------------------------------------------------------
// fp16 transpose: [Z][R][C] -> [Z][C][R]
// ---------------------------------------------------------------------------
__global__ __launch_bounds__(256) void txph(const fp16* __restrict__ in,
                                            fp16* __restrict__ o, int R, int C) {
    __shared__ fp16 t[32][33];
    int z = blockIdx.z;
    size_t zb = (size_t)z * R * C;
    int c0 = blockIdx.x * 32, r0 = blockIdx.y * 32;
    int x = threadIdx.x, y = threadIdx.y;
#pragma unroll
    for (int i = 0; i < 32; i += 8)
        t[y + i][x] = in[zb + (size_t)(r0 + y + i) * C + c0 + x];
    __syncthreads();
#pragma unroll
    for (int i = 0; i < 32; i += 8)
        o[zb + (size_t)(c0 + y + i) * R + r0 + x] = t[x][y + i];
}

// ---------------------------------------------------------------------------
// fp16 GEMM, 4-stage cp.async, hoisted frags, 1 sync/iter.
// C tile = A[128,K] * B[128,K]^T
// MODE 0: QKV -> bias, scatter fp16 q/k/v
// MODE 1: QK^T -> P~ = exp(s*scale) fp16 + atomic row sums into lsum
// MODE 2: PV -> normalize by 1/lsum[row], fp16 attnout
// MODE 3: proj -> bias + residual + transposed fp32 store
// ---------------------------------------------------------------------------
template <int MODE>
__global__ __launch_bounds__(256, 2) void gemm_fp16(
    const fp16* __restrict__ A, const fp16* __restrict__ B,
    float* __restrict__ C, fp16* __restrict__ Cf,
    int K, int ldA, int ldB, int ldC, size_t Az, size_t Bz, size_t Cz,
    const float* __restrict__ bias, const float* __restrict__ resid,
    float scale, float* __restrict__ lsum) {
    extern __shared__ __align__(16) char dynsm[];
    const uint32_t sbase = smem_u32(dynsm);

    const int tid = threadIdx.x;
    const int wid = tid >> 5;
    const int lane = tid & 31;
    const int wr = wid >> 1;
    const int wc = wid & 1;

    const int z = blockIdx.z;
    const int m0 = blockIdx.y * BM;
    const int n0 = blockIdx.x * BN;
    const fp16* tA = A + Az * z + (size_t)m0 * ldA;
    const fp16* tB = B + Bz * z + (size_t)n0 * ldB;
    const int NKB = K / BKF;

    const int crow = tid >> 1;
    const int ccol = (tid & 1) * 16;

    auto issue = [&](int kb, int stg) {
        uint32_t sb = sbase + stg * STAGEB + (crow * PAD + ccol) * 2;
        const fp16* ga = tA + (size_t)crow * ldA + kb * BKF + ccol;
        cpa16(sb, ga);
        cpa16(sb + 16, ga + 8);
        const fp16* gb = tB + (size_t)crow * ldB + kb * BKF + ccol;
        cpa16(sb + TILEB, gb);
        cpa16(sb + TILEB + 16, gb + 8);
    };

    const int lr = lane & 15, lhf = lane >> 4;
    uint32_t aoff[2], boff[4];
#pragma unroll
    for (int im = 0; im < 2; ++im)
        aoff[im] = ((wr * 32 + im * 16 + lr) * PAD + lhf * 8) * 2;
#pragma unroll
    for (int jn = 0; jn < 4; ++jn)
        boff[jn] = ((wc * 64 + jn * 16 + lr) * PAD + lhf * 8) * 2;

    float acc[2][8][4] = {};

    issue(0, 0); cpa_commit();
    if (NKB > 1) { issue(1, 1); cpa_commit(); }
    if (NKB > 2) { issue(2, 2); cpa_commit(); }

    for (int kb = 0; kb < NKB; ++kb) {
        if (kb + 3 <= NKB) cpa_wait<2>();
        else if (kb + 2 == NKB) cpa_wait<1>();
        else cpa_wait<0>();
        __syncthreads();
        if (kb + 3 < NKB) { issue(kb + 3, (kb + 3) % NSTAGE); cpa_commit(); }

        const int stg = kb % NSTAGE;
        const uint32_t sA = sbase + stg * STAGEB;
        const uint32_t sB = sA + TILEB;

        uint32_t af[2][2][4], bf[2][4][4];
#pragma unroll
        for (int ks = 0; ks < 2; ++ks) {
            const uint32_t kso = ks * 32;
            ldsm4(af[ks][0], sA + aoff[0] + kso);
            ldsm4(af[ks][1], sA + aoff[1] + kso);
#pragma unroll
            for (int jn = 0; jn < 4; ++jn) ldsm4(bf[ks][jn], sB + boff[jn] + kso);
        }
#pragma unroll
        for (int ks = 0; ks < 2; ++ks)
#pragma unroll
            for (int im = 0; im < 2; ++im)
#pragma unroll
                for (int jn = 0; jn < 4; ++jn) {
                    mma16816(acc[im][jn * 2], af[ks][im], bf[ks][jn][0], bf[ks][jn][2]);
                    mma16816(acc[im][jn * 2 + 1], af[ks][im], bf[ks][jn][1], bf[ks][jn][3]);
                }
    }
    __syncthreads();

    // ---- epilogue ----
    const int r0l = lane >> 2;
    const int c0l = (lane & 3) * 2;

    if (MODE == 0) {
        const int hB = n0 / 768;
        const int loc0 = n0 % 768;
        const int seg = loc0 >> 8;
        const int d0 = loc0 & 255;
        fp16* dst = (seg == 0) ? g_q : (seg == 1) ? g_k : g_v;
#pragma unroll
        for (int im = 0; im < 2; ++im)
#pragma unroll
            for (int jn = 0; jn < 8; ++jn)
#pragma unroll
                for (int p = 0; p < 2; ++p) {
                    int m = m0 + wr * 32 + im * 16 + r0l + p * 8;
                    int nb = wc * 64 + jn * 8 + c0l;
                    int b = m >> 10, s2 = m & 1023;
                    size_t row = ((size_t)(b * NH + hB) * SS + s2) * DK + d0 + nb;
                    __half2 h;
                    h.x = __float2half(acc[im][jn][p * 2] + bias[n0 + nb]);
                    h.y = __float2half(acc[im][jn][p * 2 + 1] + bias[n0 + nb + 1]);
                    *(__half2*)(dst + row) = h;
                }
    } else if (MODE == 1) {
        // P~ = exp(s*scale) as fp16, plus atomic row-sum accumulation
        fp16* Cb = Cf + Cz * z;
        float rsum[2][2] = {};
#pragma unroll
        for (int im = 0; im < 2; ++im)
#pragma unroll
            for (int p = 0; p < 2; ++p) {
                int m = m0 + wr * 32 + im * 16 + r0l + p * 8;
                float rs = 0.0f;
#pragma unroll
                for (int jn = 0; jn < 8; ++jn) {
                    int nb = wc * 64 + jn * 8 + c0l;
                    float p0 = __expf(acc[im][jn][p * 2] * scale);
                    float p1 = __expf(acc[im][jn][p * 2 + 1] * scale);
                    rs += p0 + p1;
                    __half2 h;
                    h.x = __float2half(p0);
                    h.y = __float2half(p1);
                    *(__half2*)(Cb + (size_t)m * ldC + n0 + nb) = h;
                }
                rsum[im][p] = rs;
            }
        // quad reduce (lanes sharing a row differ in bits 0..1)
#pragma unroll
        for (int im = 0; im < 2; ++im)
#pragma unroll
            for (int p = 0; p < 2; ++p) {
                float s = rsum[im][p];
                s += __shfl_xor_sync(0xffffffffu, s, 1);
                s += __shfl_xor_sync(0xffffffffu, s, 2);
                if ((lane & 3) == 0) {
                    int m = m0 + wr * 32 + im * 16 + r0l + p * 8;
                    atomicAdd(lsum + (size_t)z * SS + m, s);
                }
            }
    } else if (MODE == 2) {
        int b = z >> 3, h2 = z & 7;
        size_t base = (size_t)b * SS * HD + h2 * DK;
        const float* lz = lsum + (size_t)z * SS;
#pragma unroll
        for (int im = 0; im < 2; ++im)
#pragma unroll
            for (int p = 0; p < 2; ++p) {
                int m = m0 + wr * 32 + im * 16 + r0l + p * 8;
                float inv = 1.0f / lz[m];
#pragma unroll
                for (int jn = 0; jn < 8; ++jn) {
                    int nb = wc * 64 + jn * 8 + c0l;
                    size_t idx = base + (size_t)m * HD + n0 + nb;
                    __half2 h;
                    h.x = __float2half(acc[im][jn][p * 2] * inv);
                    h.y = __float2half(acc[im][jn][p * 2 + 1] * inv);
                    *(__half2*)(g_ao + idx) = h;
                }
            }
    } else {  // MODE 3
        float* sc = (float*)dynsm;  // 128 x 65 fp32 = 33.3 KB (fits 80 KB)
        const int bB = m0 >> 10;
        const int s0 = m0 & 1023;
#pragma unroll
        for (int pass = 0; pass < 2; ++pass) {
            __syncthreads();
            if (wc == pass) {
#pragma unroll
                for (int im = 0; im < 2; ++im)
#pragma unroll
                    for (int jn = 0; jn < 8; ++jn)
#pragma unroll
                        for (int p = 0; p < 2; ++p) {
                            int rloc = wr * 32 + im * 16 + r0l + p * 8;
                            int cloc = jn * 8 + c0l;
                            sc[rloc * 65 + cloc] = acc[im][jn][p * 2];
                            sc[rloc * 65 + cloc + 1] = acc[im][jn][p * 2 + 1];
                        }
            }
            __syncthreads();
            int nl = tid >> 2;
            int sblk = (tid & 3) * 32;
            int n = n0 + pass * 64 + nl;
            size_t obase = (((size_t)(bB * CC + n)) << 10) + s0 + sblk;
            float bn = bias[n];
#pragma unroll
            for (int j = 0; j < 32; j += 4) {
                float4 xr = *(const float4*)(resid + obase + j);
                float4 o;
                o.x = sc[(sblk + j + 0) * 65 + nl] + bn + xr.x;
                o.y = sc[(sblk + j + 1) * 65 + nl] + bn + xr.y;
                o.z = sc[(sblk + j + 2) * 65 + nl] + bn + xr.z;
                o.w = sc[(sblk + j + 3) * 65 + nl] + bn + xr.w;
                *(float4*)(C + obase + j) = o;
            }
        }
    }
}

// ---------------------------------------------------------------------------
extern "C" void kernel_launch(void* const* d_in, const int* in_sizes, int n_in,
                              void* d_out, int out_size) {
    const float* x  = (const float*)d_in[0];
    const float* Wp = (const float*)d_in[1];
    const float* bp = (const float*)d_in[2];
    const float* Wo = (const float*)d_in[3];
    const float* bo = (const float*)d_in[4];
    float* out = (float*)d_out;

    fp16 *xt, *WpT, *WoT, *q, *k, *v, *vt, *pp, *ao;
    float* lp;
    cudaGetSymbolAddress((void**)&xt, g_xt);
    cudaGetSymbolAddress((void**)&WpT, g_WpT);
    cudaGetSymbolAddress((void**)&WoT, g_WoT);
    cudaGetSymbolAddress((void**)&q, g_q);
    cudaGetSymbolAddress((void**)&k, g_k);
    cudaGetSymbolAddress((void**)&v, g_v);
    cudaGetSymbolAddress((void**)&vt, g_vt);
    cudaGetSymbolAddress((void**)&pp, g_p);
    cudaGetSymbolAddress((void**)&ao, g_ao);
    cudaGetSymbolAddress((void**)&lp, g_l);

    cudaFuncSetAttribute(gemm_fp16<0>, cudaFuncAttributeMaxDynamicSharedMemorySize, SMEM_DYN);
    cudaFuncSetAttribute(gemm_fp16<1>, cudaFuncAttributeMaxDynamicSharedMemorySize, SMEM_DYN);
    cudaFuncSetAttribute(gemm_fp16<2>, cudaFuncAttributeMaxDynamicSharedMemorySize, SMEM_DYN);
    cudaFuncSetAttribute(gemm_fp16<3>, cudaFuncAttributeMaxDynamicSharedMemorySize, SMEM_DYN);

    // zero the softmax row-sum accumulators (graph-capturable memset node)
    cudaMemsetAsync(lp, 0, BB * NH * SS * sizeof(float), 0);

    dim3 tb(32, 8);
    convT<<<dim3(SS / 32, CC / 32, BB), tb>>>(x, xt, CC, SS);
    convT<<<dim3(QKVN / 32, CC / 32, 1), tb>>>(Wp, WpT, CC, QKVN);
    convT<<<dim3(CC / 32, HD / 32, 1), tb>>>(Wo, WoT, HD, CC);

    // QKV projection: [8192,256] @ [6144,256]^T
    gemm_fp16<0><<<dim3(QKVN / BN, (BB * SS) / BM, 1), 256, SMEM_DYN>>>(
        xt, WpT, nullptr, nullptr, CC, CC, CC, 0, 0, 0, 0, bp, nullptr, 1.0f, nullptr);

    // V -> V^T per head
    txph<<<dim3(DK / 32, SS / 32, BB * NH), tb>>>(v, vt, SS, DK);

    // Q K^T -> P~ = exp(s/16) fp16 + row sums
    gemm_fp16<1><<<dim3(SS / BN, SS / BM, BB * NH), 256, SMEM_DYN>>>(
        q, k, nullptr, pp, DK, DK, DK, SS,
        (size_t)SS * DK, (size_t)SS * DK, (size_t)SS * SS, nullptr, nullptr,
        0.0625f, lp);

    // P~ V -> normalized attnout
    gemm_fp16<2><<<dim3(DK / BN, SS / BM, BB * NH), 256, SMEM_DYN>>>(
        pp, vt, nullptr, nullptr, SS, SS, SS, 0,
        (size_t)SS * SS, (size_t)DK * SS, 0, nullptr, nullptr, 1.0f, lp);

    // Out projection + bias + residual
    gemm_fp16<3><<<dim3(CC / BN, (BB * SS) / BM, 1), 256, SMEM_DYN>>>(
        ao, WoT, out, nullptr, HD, HD, HD, 0, 0, 0, 0, bo, x, 1.0f, nullptr);
}

// round 11
// speedup vs baseline: 2.4763x; 1.1134x over previous
#include <cuda_runtime.h>
#include <cuda_fp16.h>
#include <cstdint>
#include <cstddef>

// ---------------------------------------------------------------------------
#define BB 8
#define CC 256
#define SS 1024
#define NH 8
#define DK 256
#define HD 2048
#define QKVN 6144

#define BM 128
#define BN 128
#define BKF 32                     // K elements per block
#define PAD 40                     // fp16 per smem row (80B; ldsm conflict-free)
#define TILEB (128 * PAD * 2)      // 10240 B per tile
#define STAGEB (2 * TILEB)         // A, B
#define NSTAGE 5
#define SMEM_DYN (NSTAGE * STAGEB) // 102400 B (2 CTAs/SM: 200 KB <= 228 KB)
#define SCP 132                    // fp16 pad for V-transpose staging

typedef __half fp16;

// ---------------------------------------------------------------------------
// Device scratch (allocation-free)
// ---------------------------------------------------------------------------
__device__ __align__(128) fp16 g_xt[BB * SS * CC];        // [b*S+s][c]
__device__ __align__(128) fp16 g_WpT[QKVN * CC];          // [n][k]
__device__ __align__(128) fp16 g_WoT[CC * HD];            // [n][k]
__device__ __align__(128) fp16 g_q[BB * NH * SS * DK];    // [bh][s][d]
__device__ __align__(128) fp16 g_k[BB * NH * SS * DK];    // [bh][s][d]
__device__ __align__(128) fp16 g_v[BB * NH * DK * SS];    // [bh][d][s]  TRANSPOSED
__device__ __align__(128) fp16 g_p[(size_t)BB * NH * SS * SS]; // unnormalized exp
__device__ __align__(128) float g_l[BB * NH * SS];        // row sums of exp
__device__ __align__(128) fp16 g_ao[BB * SS * HD];        // [b*S+s][h*DK+d]

// ---------------------------------------------------------------------------
// PTX helpers
// ---------------------------------------------------------------------------
__device__ __forceinline__ uint32_t smem_u32(const void* p) {
    uint32_t a;
    asm("{ .reg .u64 t; cvta.to.shared.u64 t, %1; cvt.u32.u64 %0, t; }"
        : "=r"(a) : "l"(p));
    return a;
}
__device__ __forceinline__ void cpa16(uint32_t dst, const void* src) {
    asm volatile("cp.async.cg.shared.global [%0], [%1], 16;"
                 :: "r"(dst), "l"(src) : "memory");
}
__device__ __forceinline__ void cpa_commit() {
    asm volatile("cp.async.commit_group;" ::: "memory");
}
template <int N> __device__ __forceinline__ void cpa_wait() {
    asm volatile("cp.async.wait_group %0;" :: "n"(N) : "memory");
}
__device__ __forceinline__ void ldsm4(uint32_t* r, uint32_t addr) {
    asm volatile("ldmatrix.sync.aligned.m8n8.x4.shared.b16 {%0,%1,%2,%3}, [%4];"
                 : "=r"(r[0]), "=r"(r[1]), "=r"(r[2]), "=r"(r[3]) : "r"(addr));
}
__device__ __forceinline__ void mma16816(float* d, const uint32_t* a,
                                         uint32_t b0, uint32_t b1) {
    asm volatile(
        "mma.sync.aligned.m16n8k16.row.col.f32.f16.f16.f32 "
        "{%0,%1,%2,%3}, {%4,%5,%6,%7}, {%8,%9}, {%0,%1,%2,%3};"
        : "+f"(d[0]), "+f"(d[1]), "+f"(d[2]), "+f"(d[3])
        : "r"(a[0]), "r"(a[1]), "r"(a[2]), "r"(a[3]), "r"(b0), "r"(b1));
}

// ---------------------------------------------------------------------------
// fp32 [Z][R][C] -> transposed fp16 [Z][C][R]
// ---------------------------------------------------------------------------
__global__ __launch_bounds__(256) void convT(const float* __restrict__ in,
                                             fp16* __restrict__ o, int R, int C) {
    __shared__ float t[32][33];
    int z = blockIdx.z;
    const float* I = in + (size_t)z * R * C;
    size_t ob = (size_t)z * R * C;
    int c0 = blockIdx.x * 32, r0 = blockIdx.y * 32;
    int x = threadIdx.x, y = threadIdx.y;
#pragma unroll
    for (int i = 0; i < 32; i += 8)
        t[y + i][x] = I[(size_t)(r0 + y + i) * C + c0 + x];
    __syncthreads();
#pragma unroll
    for (int i = 0; i < 32; i += 8)
        o[ob + (size_t)(c0 + y + i) * R + r0 + x] = __float2half(t[x][y + i]);
}

// ---------------------------------------------------------------------------
// fp16 GEMM, 5-stage cp.async, split A/B issue, 1 sync/iter.
// C tile = A[128,K] * B[128,K]^T
// MODE 0: QKV -> bias; Q/K scattered; V written TRANSPOSED via smem staging
// MODE 1: QK^T -> P~ = exp(s*scale) fp16 + atomic row sums into lsum
// MODE 2: PV -> normalize by 1/lsum[row], fp16 attnout
// MODE 3: proj -> bias + residual + transposed fp32 store
// ---------------------------------------------------------------------------
template <int MODE>
__global__ __launch_bounds__(256, 2) void gemm_fp16(
    const fp16* __restrict__ A, const fp16* __restrict__ B,
    float* __restrict__ C, fp16* __restrict__ Cf,
    int K, int ldA, int ldB, int ldC, size_t Az, size_t Bz, size_t Cz,
    const float* __restrict__ bias, const float* __restrict__ resid,
    float scale, float* __restrict__ lsum) {
    extern __shared__ __align__(16) char dynsm[];
    const uint32_t sbase = smem_u32(dynsm);

    const int tid = threadIdx.x;
    const int wid = tid >> 5;
    const int lane = tid & 31;
    const int wr = wid >> 1;
    const int wc = wid & 1;

    const int z = blockIdx.z;
    const int m0 = blockIdx.y * BM;
    const int n0 = blockIdx.x * BN;
    const fp16* tA = A + Az * z + (size_t)m0 * ldA;
    const fp16* tB = B + Bz * z + (size_t)n0 * ldB;
    const int NKB = K / BKF;

    const int crow = tid >> 1;
    const int ccol = (tid & 1) * 16;

    auto issueA = [&](int kb, int stg) {
        uint32_t sb = sbase + stg * STAGEB + (crow * PAD + ccol) * 2;
        const fp16* ga = tA + (size_t)crow * ldA + kb * BKF + ccol;
        cpa16(sb, ga);
        cpa16(sb + 16, ga + 8);
    };
    auto issueB = [&](int kb, int stg) {
        uint32_t sb = sbase + stg * STAGEB + TILEB + (crow * PAD + ccol) * 2;
        const fp16* gb = tB + (size_t)crow * ldB + kb * BKF + ccol;
        cpa16(sb, gb);
        cpa16(sb + 16, gb + 8);
    };

    const int lr = lane & 15, lhf = lane >> 4;
    uint32_t aoff[2], boff[4];
#pragma unroll
    for (int im = 0; im < 2; ++im)
        aoff[im] = ((wr * 32 + im * 16 + lr) * PAD + lhf * 8) * 2;
#pragma unroll
    for (int jn = 0; jn < 4; ++jn)
        boff[jn] = ((wc * 64 + jn * 16 + lr) * PAD + lhf * 8) * 2;

    float acc[2][8][4] = {};

    // prologue: prefetch 4 stages
#pragma unroll
    for (int s = 0; s < 4; ++s) {
        issueA(s, s); issueB(s, s); cpa_commit();
    }

    for (int kb = 0; kb < NKB; ++kb) {
        if (kb + 4 <= NKB) cpa_wait<3>();
        else if (kb + 3 == NKB) cpa_wait<2>();
        else if (kb + 2 == NKB) cpa_wait<1>();
        else cpa_wait<0>();
        __syncthreads();

        const bool pf = (kb + 4 < NKB);
        const int pstg = (kb + 4) % NSTAGE;
        if (pf) issueA(kb + 4, pstg);

        const int stg = kb % NSTAGE;
        const uint32_t sA = sbase + stg * STAGEB;
        const uint32_t sB = sA + TILEB;

        uint32_t af[2][2][4], bf[2][4][4];
#pragma unroll
        for (int ks = 0; ks < 2; ++ks) {
            const uint32_t kso = ks * 32;
            ldsm4(af[ks][0], sA + aoff[0] + kso);
            ldsm4(af[ks][1], sA + aoff[1] + kso);
#pragma unroll
            for (int jn = 0; jn < 4; ++jn) ldsm4(bf[ks][jn], sB + boff[jn] + kso);
        }

        if (pf) issueB(kb + 4, pstg);

#pragma unroll
        for (int ks = 0; ks < 2; ++ks)
#pragma unroll
            for (int im = 0; im < 2; ++im)
#pragma unroll
                for (int jn = 0; jn < 4; ++jn) {
                    mma16816(acc[im][jn * 2], af[ks][im], bf[ks][jn][0], bf[ks][jn][2]);
                    mma16816(acc[im][jn * 2 + 1], af[ks][im], bf[ks][jn][1], bf[ks][jn][3]);
                }
        if (pf) cpa_commit();
    }
    __syncthreads();

    // ---- epilogue ----
    const int r0l = lane >> 2;
    const int c0l = (lane & 3) * 2;

    if (MODE == 0) {
        const int hB = n0 / 768;
        const int loc0 = n0 % 768;
        const int seg = loc0 >> 8;
        const int d0 = loc0 & 255;
        if (seg < 2) {
            fp16* dst = (seg == 0) ? g_q : g_k;
#pragma unroll
            for (int im = 0; im < 2; ++im)
#pragma unroll
                for (int jn = 0; jn < 8; ++jn)
#pragma unroll
                    for (int p = 0; p < 2; ++p) {
                        int m = m0 + wr * 32 + im * 16 + r0l + p * 8;
                        int nb = wc * 64 + jn * 8 + c0l;
                        int b = m >> 10, s2 = m & 1023;
                        size_t row = ((size_t)(b * NH + hB) * SS + s2) * DK + d0 + nb;
                        __half2 h;
                        h.x = __float2half(acc[im][jn][p * 2] + bias[n0 + nb]);
                        h.y = __float2half(acc[im][jn][p * 2 + 1] + bias[n0 + nb + 1]);
                        *(__half2*)(dst + row) = h;
                    }
        } else {
            // V: stage [m][d] in smem, write transposed [d][s] coalesced
            fp16* sc = (fp16*)dynsm;  // 128 x SCP fp16 = 33.8 KB
#pragma unroll
            for (int im = 0; im < 2; ++im)
#pragma unroll
                for (int jn = 0; jn < 8; ++jn)
#pragma unroll
                    for (int p = 0; p < 2; ++p) {
                        int ml = wr * 32 + im * 16 + r0l + p * 8;
                        int nb = wc * 64 + jn * 8 + c0l;
                        sc[ml * SCP + nb] =
                            __float2half(acc[im][jn][p * 2] + bias[n0 + nb]);
                        sc[ml * SCP + nb + 1] =
                            __float2half(acc[im][jn][p * 2 + 1] + bias[n0 + nb + 1]);
                    }
            __syncthreads();
            const int b = m0 >> 10;
            const int s0 = m0 & 1023;
            const int d = tid & 127;          // local d 0..127
            const int mh = (tid >> 7) * 64;   // m half: 0 or 64
            fp16* vrow = g_v + ((size_t)(b * NH + hB) * DK + d0 + d) * SS + s0 + mh;
#pragma unroll
            for (int j = 0; j < 64; j += 2) {
                __half2 h;
                h.x = sc[(mh + j) * SCP + d];
                h.y = sc[(mh + j + 1) * SCP + d];
                *(__half2*)(vrow + j) = h;
            }
        }
    } else if (MODE == 1) {
        fp16* Cb = Cf + Cz * z;
        float rsum[2][2] = {};
#pragma unroll
        for (int im = 0; im < 2; ++im)
#pragma unroll
            for (int p = 0; p < 2; ++p) {
                int m = m0 + wr * 32 + im * 16 + r0l + p * 8;
                float rs = 0.0f;
#pragma unroll
                for (int jn = 0; jn < 8; ++jn) {
                    int nb = wc * 64 + jn * 8 + c0l;
                    float p0 = __expf(acc[im][jn][p * 2] * scale);
                    float p1 = __expf(acc[im][jn][p * 2 + 1] * scale);
                    rs += p0 + p1;
                    __half2 h;
                    h.x = __float2half(p0);
                    h.y = __float2half(p1);
                    *(__half2*)(Cb + (size_t)m * ldC + n0 + nb) = h;
                }
                rsum[im][p] = rs;
            }
#pragma unroll
        for (int im = 0; im < 2; ++im)
#pragma unroll
            for (int p = 0; p < 2; ++p) {
                float s = rsum[im][p];
                s += __shfl_xor_sync(0xffffffffu, s, 1);
                s += __shfl_xor_sync(0xffffffffu, s, 2);
                if ((lane & 3) == 0) {
                    int m = m0 + wr * 32 + im * 16 + r0l + p * 8;
                    atomicAdd(lsum + (size_t)z * SS + m, s);
                }
            }
    } else if (MODE == 2) {
        int b = z >> 3, h2 = z & 7;
        size_t base = (size_t)b * SS * HD + h2 * DK;
        const float* lz = lsum + (size_t)z * SS;
#pragma unroll
        for (int im = 0; im < 2; ++im)
#pragma unroll
            for (int p = 0; p < 2; ++p) {
                int m = m0 + wr * 32 + im * 16 + r0l + p * 8;
                float inv = 1.0f / lz[m];
#pragma unroll
                for (int jn = 0; jn < 8; ++jn) {
                    int nb = wc * 64 + jn * 8 + c0l;
                    size_t idx = base + (size_t)m * HD + n0 + nb;
                    __half2 h;
                    h.x = __float2half(acc[im][jn][p * 2] * inv);
                    h.y = __float2half(acc[im][jn][p * 2 + 1] * inv);
                    *(__half2*)(g_ao + idx) = h;
                }
            }
    } else {  // MODE 3
        float* sc = (float*)dynsm;  // 128 x 65 fp32 = 33.3 KB (fits 100 KB)
        const int bB = m0 >> 10;
        const int s0 = m0 & 1023;
#pragma unroll
        for (int pass = 0; pass < 2; ++pass) {
            __syncthreads();
            if (wc == pass) {
#pragma unroll
                for (int im = 0; im < 2; ++im)
#pragma unroll
                    for (int jn = 0; jn < 8; ++jn)
#pragma unroll
                        for (int p = 0; p < 2; ++p) {
                            int rloc = wr * 32 + im * 16 + r0l + p * 8;
                            int cloc = jn * 8 + c0l;
                            sc[rloc * 65 + cloc] = acc[im][jn][p * 2];
                            sc[rloc * 65 + cloc + 1] = acc[im][jn][p * 2 + 1];
                        }
            }
            __syncthreads();
            int nl = tid >> 2;
            int sblk = (tid & 3) * 32;
            int n = n0 + pass * 64 + nl;
            size_t obase = (((size_t)(bB * CC + n)) << 10) + s0 + sblk;
            float bn = bias[n];
#pragma unroll
            for (int j = 0; j < 32; j += 4) {
                float4 xr = *(const float4*)(resid + obase + j);
                float4 o;
                o.x = sc[(sblk + j + 0) * 65 + nl] + bn + xr.x;
                o.y = sc[(sblk + j + 1) * 65 + nl] + bn + xr.y;
                o.z = sc[(sblk + j + 2) * 65 + nl] + bn + xr.z;
                o.w = sc[(sblk + j + 3) * 65 + nl] + bn + xr.w;
                *(float4*)(C + obase + j) = o;
            }
        }
    }
}

// ---------------------------------------------------------------------------
extern "C" void kernel_launch(void* const* d_in, const int* in_sizes, int n_in,
                              void* d_out, int out_size) {
    const float* x  = (const float*)d_in[0];
    const float* Wp = (const float*)d_in[1];
    const float* bp = (const float*)d_in[2];
    const float* Wo = (const float*)d_in[3];
    const float* bo = (const float*)d_in[4];
    float* out = (float*)d_out;

    fp16 *xt, *WpT, *WoT, *q, *k, *v, *pp, *ao;
    float* lp;
    cudaGetSymbolAddress((void**)&xt, g_xt);
    cudaGetSymbolAddress((void**)&WpT, g_WpT);
    cudaGetSymbolAddress((void**)&WoT, g_WoT);
    cudaGetSymbolAddress((void**)&q, g_q);
    cudaGetSymbolAddress((void**)&k, g_k);
    cudaGetSymbolAddress((void**)&v, g_v);
    cudaGetSymbolAddress((void**)&pp, g_p);
    cudaGetSymbolAddress((void**)&ao, g_ao);
    cudaGetSymbolAddress((void**)&lp, g_l);

    cudaFuncSetAttribute(gemm_fp16<0>, cudaFuncAttributeMaxDynamicSharedMemorySize, SMEM_DYN);
    cudaFuncSetAttribute(gemm_fp16<1>, cudaFuncAttributeMaxDynamicSharedMemorySize, SMEM_DYN);
    cudaFuncSetAttribute(gemm_fp16<2>, cudaFuncAttributeMaxDynamicSharedMemorySize, SMEM_DYN);
    cudaFuncSetAttribute(gemm_fp16<3>, cudaFuncAttributeMaxDynamicSharedMemorySize, SMEM_DYN);

    cudaMemsetAsync(lp, 0, BB * NH * SS * sizeof(float), 0);

    dim3 tb(32, 8);
    convT<<<dim3(SS / 32, CC / 32, BB), tb>>>(x, xt, CC, SS);
    convT<<<dim3(QKVN / 32, CC / 32, 1), tb>>>(Wp, WpT, CC, QKVN);
    convT<<<dim3(CC / 32, HD / 32, 1), tb>>>(Wo, WoT, HD, CC);

    // QKV projection: [8192,256] @ [6144,256]^T  (V written transposed)
    gemm_fp16<0><<<dim3(QKVN / BN, (BB * SS) / BM, 1), 256, SMEM_DYN>>>(
        xt, WpT, nullptr, nullptr, CC, CC, CC, 0, 0, 0, 0, bp, nullptr, 1.0f, nullptr);

    // Q K^T -> P~ = exp(s/16) fp16 + row sums
    gemm_fp16<1><<<dim3(SS / BN, SS / BM, BB * NH), 256, SMEM_DYN>>>(
        q, k, nullptr, pp, DK, DK, DK, SS,
        (size_t)SS * DK, (size_t)SS * DK, (size_t)SS * SS, nullptr, nullptr,
        0.0625f, lp);

    // P~ V -> normalized attnout (B = V^T, [bh][d][s])
    gemm_fp16<2><<<dim3(DK / BN, SS / BM, BB * NH), 256, SMEM_DYN>>>(
        pp, v, nullptr, nullptr, SS, SS, SS, 0,
        (size_t)SS * SS, (size_t)DK * SS, 0, nullptr, nullptr, 1.0f, lp);

    // Out projection + bias + residual
    gemm_fp16<3><<<dim3(CC / BN, (BB * SS) / BM, 1), 256, SMEM_DYN>>>(
        ao, WoT, out, nullptr, HD, HD, HD, 0, 0, 0, 0, bo, x, 1.0f, nullptr);
}